// round 4
// baseline (speedup 1.0000x reference)
#include <cuda_runtime.h>
#include <math.h>

#define TT 128
#define NN 128
#define CC 512
#define DD 1024
#define KK 512
#define ND (NN*DD)      // 131072
#define NK (NN*KK)      // 65536
#define NB 128          // persistent grid size (<= 148 SMs, all co-resident)
#define TPB 512

// ---------------- device scratch (static: no runtime allocation) ----------------
__device__ float g_XW[TT*NN*DD];     // x@enc_Wx + bx + bh  (64MB)
__device__ float g_ench[TT*NN*DD];   // encoder hidden states (64MB)
__device__ float g_WaT[DD*DD];       // W_alpha transposed
__device__ float g_M1[DD*KK];        // dec_Wy @ Wc_top
__device__ float g_b2[KK];           // dby @ Wc_top + bc
__device__ float g_h[ND];            // current hidden state
__device__ float g_u[ND];            // h @ WaT
__device__ float g_c[ND];            // context vectors
__device__ float g_e[TT*NN];         // attention logits [t][n]
__device__ float g_pA[16*ND];        // split-K partials (encoder / u)
__device__ float g_pB[8*ND];         // split-K partials (dec h)
__device__ float g_pC[32*NK];        // split-K partials (y)
__device__ int   g_idx[NN];          // argmax feedback index
__device__ unsigned g_barcnt;
__device__ volatile unsigned g_barphase;

// ---------------- init (runs every launch: resets state + barrier) ----------------
__global__ void init_kernel() {
    int i = blockIdx.x * blockDim.x + threadIdx.x;
    if (i < ND) g_h[i] = 0.f;
    if (i < NN) g_idx[i] = CC - 2;
    if (i == 0) { g_barcnt = 0; g_barphase = 0; }
}

// ---------------- transpose W_alpha ----------------
__global__ void transpose_kernel(const float* __restrict__ W) {
    __shared__ float tile[32][33];
    int x = blockIdx.x*32 + threadIdx.x;
    int y = blockIdx.y*32 + threadIdx.y;
    tile[threadIdx.y][threadIdx.x] = W[y*DD + x];
    __syncthreads();
    int xo = blockIdx.y*32 + threadIdx.x;
    int yo = blockIdx.x*32 + threadIdx.y;
    g_WaT[yo*DD + xo] = tile[threadIdx.x][threadIdx.y];
}

// ---------------- b2 = dby @ Wc_top + bc ----------------
__global__ void b2_kernel(const float* __restrict__ dby, const float* __restrict__ Wc,
                          const float* __restrict__ bc) {
    int k = threadIdx.x;  // 512
    float s = bc[k];
    for (int j = 0; j < KK; j++) s += dby[j] * Wc[j*KK + k];
    g_b2[k] = s;
}

// ---------------- 128x128 tile GEMM core (512 thr, 8x4/thread, FFMA-bound) ------
// Computes out[r][colBase+c] (+bias) for rows 0..127 of A, k range [k0, k0+klen).
__device__ __forceinline__ void tile_gemm(
    const float* __restrict__ A, int lda,
    const float* __restrict__ B, int ldb,
    int k0, int klen, int colBase,
    float* __restrict__ out, int ldo,
    const float* __restrict__ bias1, const float* __restrict__ bias2,
    float* sAs, float* sBs)
{
    const int tid = threadIdx.x;
    const int tx = tid & 31;         // 32 col groups of 4
    const int ty = tid >> 5;         // 16 row groups of 8
    float acc[8][4];
    #pragma unroll
    for (int r = 0; r < 8; r++)
        #pragma unroll
        for (int c = 0; c < 4; c++) acc[r][c] = 0.f;

    for (int kk = k0; kk < k0 + klen; kk += 16) {
        // load A tile (128 rows x 16 k), transpose to k-major in SMEM
        {
            int r = tid >> 2, kq = (tid & 3) * 4;
            float4 v = *(const float4*)&A[(size_t)r*lda + kk + kq];
            sAs[(kq+0)*128 + r] = v.x;
            sAs[(kq+1)*128 + r] = v.y;
            sAs[(kq+2)*128 + r] = v.z;
            sAs[(kq+3)*128 + r] = v.w;
        }
        // load B tile (16 k x 128 cols), coalesced
        {
            int k = tid >> 5, c = (tid & 31) * 4;
            *(float4*)&sBs[k*128 + c] = *(const float4*)&B[(size_t)(kk+k)*ldb + colBase + c];
        }
        __syncthreads();
        #pragma unroll
        for (int k = 0; k < 16; k++) {
            float4 b  = *(const float4*)&sBs[k*128 + tx*4];
            float4 a0 = *(const float4*)&sAs[k*128 + ty*8];
            float4 a1 = *(const float4*)&sAs[k*128 + ty*8 + 4];
            float av[8] = {a0.x,a0.y,a0.z,a0.w,a1.x,a1.y,a1.z,a1.w};
            #pragma unroll
            for (int r = 0; r < 8; r++) {
                acc[r][0] += av[r]*b.x;
                acc[r][1] += av[r]*b.y;
                acc[r][2] += av[r]*b.z;
                acc[r][3] += av[r]*b.w;
            }
        }
        __syncthreads();
    }
    float bb[4] = {0.f, 0.f, 0.f, 0.f};
    if (bias1) {
        #pragma unroll
        for (int c = 0; c < 4; c++) {
            bb[c] = bias1[colBase + tx*4 + c];
            if (bias2) bb[c] += bias2[colBase + tx*4 + c];
        }
    }
    #pragma unroll
    for (int r = 0; r < 8; r++) {
        float4 v = make_float4(acc[r][0]+bb[0], acc[r][1]+bb[1], acc[r][2]+bb[2], acc[r][3]+bb[3]);
        *(float4*)&out[(size_t)(ty*8 + r)*ldo + colBase + tx*4] = v;
    }
}

// ---------------- setup GEMMs (parallel, full-K): which=0 -> g_XW, which=1 -> g_M1 --
__global__ __launch_bounds__(512)
void setup_gemm_kernel(const float* __restrict__ A, int lda,
                       const float* __restrict__ B, int ldb, int Ktot,
                       const float* __restrict__ b1, const float* __restrict__ b2,
                       int which) {
    __shared__ float sAs[2048];
    __shared__ float sBs[2048];
    float* C  = which ? g_M1 : g_XW;
    int   ldc = which ? KK : DD;
    tile_gemm(A + (size_t)blockIdx.y*128*lda, lda, B, ldb, 0, Ktot,
              blockIdx.x*128, C + (size_t)blockIdx.y*128*ldc, ldc, b1, b2, sAs, sBs);
}

// ---------------- software grid barrier ----------------
__device__ __forceinline__ void gsync(unsigned phase) {
    __syncthreads();
    if (threadIdx.x == 0) {
        __threadfence();
        unsigned t = atomicAdd(&g_barcnt, 1u);
        if (t == NB - 1) {
            g_barcnt = 0;
            __threadfence();
            g_barphase = phase;
        } else {
            while (g_barphase < phase) { }
        }
        __threadfence();
    }
    __syncthreads();
}

// ---------------- persistent megakernel: encoder + decoder ----------------
__global__ __launch_bounds__(TPB, 1)
void mega_kernel(const float* __restrict__ eWh,
                 const float* __restrict__ dWx, const float* __restrict__ dbx,
                 const float* __restrict__ dWh, const float* __restrict__ dbh,
                 const float* __restrict__ Wc,
                 float* __restrict__ out_y, float* __restrict__ out_a) {
    __shared__ float sAs[2048];
    __shared__ float sBs[2048];
    __shared__ float s_sm[TT];
    __shared__ float s_red;
    __shared__ float s_v[TPB];
    __shared__ int   s_i[TPB];
    const int bid = blockIdx.x;
    const int tid = threadIdx.x;
    unsigned pc = 0;

    // ======== encoder: 128 sequential steps ========
    for (int t = 0; t < TT; t++) {
        // A: partial of h @ eWh (8 col tiles x 16 k-splits of 64)
        {
            int col = bid & 7, ks = bid >> 3;
            tile_gemm(g_h, DD, eWh, DD, ks*64, 64, col*128,
                      g_pA + (size_t)ks*ND, DD, nullptr, nullptr, sAs, sBs);
        }
        gsync(++pc);
        // B: h = relu(XW[t] + sum partials), also store into ench[t]
        #pragma unroll
        for (int it = 0; it < 2; it++) {
            int i = bid*TPB + tid + it*(NB*TPB);
            float s = g_XW[(size_t)t*ND + i];
            #pragma unroll
            for (int p = 0; p < 16; p++) s += g_pA[(size_t)p*ND + i];
            float h = fmaxf(s, 0.f);
            g_h[i] = h;
            g_ench[(size_t)t*ND + i] = h;
        }
        gsync(++pc);
    }

    // ======== decoder: 128 sequential steps ========
    for (int step = 0; step < TT; step++) {
        // A: partials of u = h@WaT (mat 0) and hpart = h@dWh (mat 1)
        {
            int mat = bid & 1, col = (bid >> 1) & 7, ks = bid >> 4;  // 2 x 8 x 8
            const float* B = mat ? dWh : g_WaT;
            float* outp = (mat ? g_pB : g_pA) + (size_t)ks*ND;
            tile_gemm(g_h, DD, B, DD, ks*128, 128, col*128, outp, DD,
                      nullptr, nullptr, sAs, sBs);
        }
        gsync(++pc);
        // B: u = sum; h = relu(sum + dWx[idx[n]] + dbx + dbh)
        #pragma unroll
        for (int it = 0; it < 2; it++) {
            int i = bid*TPB + tid + it*(NB*TPB);
            float su = 0.f, sh = 0.f;
            #pragma unroll
            for (int p = 0; p < 8; p++) {
                su += g_pA[(size_t)p*ND + i];
                sh += g_pB[(size_t)p*ND + i];
            }
            g_u[i] = su;
            int n = i >> 10, j = i & (DD-1);
            sh += dWx[(size_t)g_idx[n]*DD + j] + dbx[j] + dbh[j];
            g_h[i] = fmaxf(sh, 0.f);
        }
        gsync(++pc);
        // C: attention logits e[t,n] = ench[t,n,:] . u[n,:]  (warp per row)
        {
            int w = tid >> 5, lane = tid & 31;
            int gw = bid*16 + w;
            for (int row = gw; row < TT*NN; row += NB*16) {
                const float4* eh = (const float4*)(g_ench + (size_t)row*DD);
                const float4* uu = (const float4*)(g_u + (size_t)(row & (NN-1))*DD);
                float acc = 0.f;
                #pragma unroll
                for (int q = 0; q < 8; q++) {
                    float4 a = eh[lane + q*32];
                    float4 b = uu[lane + q*32];
                    acc += a.x*b.x + a.y*b.y + a.z*b.z + a.w*b.w;
                }
                #pragma unroll
                for (int s = 16; s; s >>= 1) acc += __shfl_xor_sync(0xffffffffu, acc, s);
                if (lane == 0) g_e[row] = acc;
            }
        }
        gsync(++pc);
        // D: per-n softmax over t + context c[n,:]; emit a_ij slice
        {
            int n = bid;
            if (tid < TT) s_sm[tid] = g_e[tid*NN + n];
            __syncthreads();
            if (tid < 32) {
                float m = fmaxf(fmaxf(s_sm[tid], s_sm[tid+32]),
                                fmaxf(s_sm[tid+64], s_sm[tid+96]));
                #pragma unroll
                for (int s = 16; s; s >>= 1) m = fmaxf(m, __shfl_xor_sync(0xffffffffu, m, s));
                if (tid == 0) s_red = m;
            }
            __syncthreads();
            float bm = s_red;
            if (tid < TT) s_sm[tid] = expf(s_sm[tid] - bm);
            __syncthreads();
            if (tid < 32) {
                float s = s_sm[tid] + s_sm[tid+32] + s_sm[tid+64] + s_sm[tid+96];
                #pragma unroll
                for (int sh = 16; sh; sh >>= 1) s += __shfl_xor_sync(0xffffffffu, s, sh);
                if (tid == 0) s_red = s;
            }
            __syncthreads();
            float inv = 1.f / s_red;
            if (tid < TT) {
                float a = s_sm[tid] * inv;
                s_sm[tid] = a;
                out_a[(size_t)step*TT*NN + tid*NN + n] = a;
            }
            __syncthreads();
            #pragma unroll 1
            for (int d = tid; d < DD; d += TPB) {
                const float* p = g_ench + (size_t)n*DD + d;
                float acc = 0.f;
                #pragma unroll 4
                for (int t2 = 0; t2 < TT; t2++) acc += s_sm[t2] * p[(size_t)t2*ND];
                g_c[n*DD + d] = acc;
            }
        }
        gsync(++pc);
        // E: y partials: mat0 h@M1, mat1 c@Wc_bot   (2 x 4 col tiles x 16 k-splits)
        {
            int tilei = bid & 7, ks = bid >> 3;
            int mat = tilei >> 2, col = tilei & 3;
            const float* A = mat ? g_c : g_h;
            const float* B = mat ? (Wc + (size_t)KK*KK) : g_M1;
            tile_gemm(A, DD, B, KK, ks*64, 64, col*128,
                      g_pC + (size_t)(mat*16 + ks)*NK, KK, nullptr, nullptr, sAs, sBs);
        }
        gsync(++pc);
        // F: y = b2 + sum partials; write out; argmax -> idx.
        // (no barrier needed here: next phase touching F's data is B', which is
        //  after the post-A' gsync, and F precedes A' in program order per CTA)
        {
            int n = bid;
            float v = g_b2[tid];
            #pragma unroll
            for (int p = 0; p < 32; p++) v += g_pC[(size_t)p*NK + n*KK + tid];
            out_y[(size_t)step*NK + n*KK + tid] = v;
            s_v[tid] = v; s_i[tid] = tid;
            __syncthreads();
            for (int s = 256; s; s >>= 1) {
                if (tid < s) {
                    float v2 = s_v[tid+s]; int i2 = s_i[tid+s];
                    if (v2 > s_v[tid] || (v2 == s_v[tid] && i2 < s_i[tid])) {
                        s_v[tid] = v2; s_i[tid] = i2;
                    }
                }
                __syncthreads();
            }
            if (tid == 0) g_idx[n] = s_i[0];
            __syncthreads();
        }
    }
}

// ---------------- host launch: 6 graph nodes total ----------------
extern "C" void kernel_launch(void* const* d_in, const int* in_sizes, int n_in,
                              void* d_out, int out_size) {
    const float* x      = (const float*)d_in[0];
    const float* eWx    = (const float*)d_in[1];
    const float* ebx    = (const float*)d_in[2];
    const float* eWh    = (const float*)d_in[3];
    const float* ebh    = (const float*)d_in[4];
    const float* dWx    = (const float*)d_in[5];
    const float* dbx    = (const float*)d_in[6];
    const float* dWh    = (const float*)d_in[7];
    const float* dbh    = (const float*)d_in[8];
    const float* dWy    = (const float*)d_in[9];
    const float* dby    = (const float*)d_in[10];
    const float* Walpha = (const float*)d_in[11];
    const float* Wc     = (const float*)d_in[12];
    const float* bc     = (const float*)d_in[13];
    float* out   = (float*)d_out;
    float* out_y = out;                            // (T, N, K)
    float* out_a = out + (size_t)TT*NN*KK;         // (T_dec, T_enc, N)

    init_kernel<<<(ND + 255)/256, 256>>>();
    transpose_kernel<<<dim3(32,32), dim3(32,32)>>>(Walpha);
    // XW = x @ enc_Wx + (ebx + ebh): (16384 x 1024), K=512
    setup_gemm_kernel<<<dim3(DD/128, TT*NN/128), 512>>>(x, CC, eWx, DD, CC, ebx, ebh, 0);
    // M1 = dec_Wy @ Wc_top: (1024 x 512), K=512
    setup_gemm_kernel<<<dim3(KK/128, DD/128), 512>>>(dWy, KK, Wc, KK, KK, nullptr, nullptr, 1);
    // b2 = dby @ Wc_top + bc
    b2_kernel<<<1, KK>>>(dby, Wc, bc);
    // everything else: one persistent kernel
    mega_kernel<<<NB, TPB>>>(eWh, dWx, dbx, dWh, dbh, Wc, out_y, out_a);
}